// round 3
// baseline (speedup 1.0000x reference)
#include <cuda_runtime.h>
#include <cstdint>

// Problem constants
#define Bq   64
#define Sq   128
#define Tq   64
#define Hq   1024
#define Eq   512
#define Vq   16000
#define ENCq 2048
#define KXq  (Eq + ENCq)   // 2560
#define G3q  (3 * Hq)      // 3072

// ---------------------------------------------------------------------------
// Scratch (device globals; runtime allocation is forbidden)
// ---------------------------------------------------------------------------
#define OFF_EP   0
#define OFF_H0   (OFF_EP + Bq*Sq*Hq)
#define OFF_H1   (OFF_H0 + Bq*Hq)
#define OFF_Q    (OFF_H1 + Bq*Hq)
#define OFF_X    (OFF_Q  + Bq*Hq)
#define OFF_GI   (OFF_X  + Bq*KXq)
#define OFF_GH   (OFF_GI + Bq*G3q)
#define OFF_PART (OFF_GH + Bq*G3q)
#define SCR_TOTAL (OFF_PART + 16*64*3072)

__device__ float g_scr[SCR_TOTAL];
__device__ int   g_tok[Bq * Tq];

// ---------------------------------------------------------------------------
// Fast math helpers (accurate to ~1e-6 rel; MUFU-based)
// ---------------------------------------------------------------------------
__device__ __forceinline__ float tanh_fast(float x) {
    float e = __expf(2.0f * x);
    return 1.0f - __fdividef(2.0f, e + 1.0f);
}
__device__ __forceinline__ float sigmoid_fast(float x) {
    return __fdividef(1.0f, 1.0f + __expf(-x));
}

// ---------------------------------------------------------------------------
// Token prep: detect int64 vs int32 target layout, build shifted token matrix
// tokens[b][0] = SOS(1); tokens[b][t] = target[b][t-1]
// Detection: if target is little-endian int64 with values < 2^31, every odd
// 32-bit word is zero; if int32, odd words are random token ids (all-zero
// probability ~0 over 2048 words).
// ---------------------------------------------------------------------------
__global__ void prep_tokens_kernel(const int* __restrict__ tgt_raw,
                                   int* __restrict__ tok) {
    __shared__ int s_nonzero;
    if (threadIdx.x == 0) s_nonzero = 0;
    __syncthreads();
    int c = 0;
    for (int i = threadIdx.x; i < (Bq * Tq) / 2; i += blockDim.x)
        if (tgt_raw[2 * i + 1] != 0) c++;
    if (c) atomicAdd(&s_nonzero, c);
    __syncthreads();
    const bool is64 = (s_nonzero == 0);
    const long long* tgt64 = (const long long*)tgt_raw;
    for (int i = threadIdx.x; i < Bq * Tq; i += blockDim.x) {
        int b = i / Tq, t = i % Tq;
        int val;
        if (t == 0) {
            val = 1;  // SOS
        } else {
            int src = b * Tq + (t - 1);
            val = is64 ? (int)tgt64[src] : tgt_raw[src];
        }
        tok[i] = val;
    }
}

__global__ void copy_kernel(const float* __restrict__ src,
                            float* __restrict__ dst, int n) {
    int i = blockIdx.x * blockDim.x + threadIdx.x;
    if (i < n) dst[i] = src[i];
}

// ---------------------------------------------------------------------------
// Generic tiled fp32 GEMM:  C[M,N] = A[M,K] @ W[N,K]^T  (+ bias)
// BM=64, BN=128, BK=16, 256 threads, 4x8 microtile per thread.
// Split-K via blockIdx.z: writes dense partials part[z][64][N] when
// Cpart != null (deterministic reduce in a second kernel); else writes
// C (+bias) directly with row stride ldc. Shapes are exact tile multiples.
// ---------------------------------------------------------------------------
__global__ __launch_bounds__(256)
void gemm64(const float* __restrict__ A, int lda,
            const float* __restrict__ W, int ldw,
            const float* __restrict__ bias,
            float* __restrict__ C, long long ldc,
            float* __restrict__ Cpart,
            int N, int Kc) {
    __shared__ float As[16][64];
    __shared__ float Ws[16][128];

    const int m0 = blockIdx.y * 64;
    const int n0 = blockIdx.x * 128;
    const int kb = blockIdx.z * Kc;
    const int tid = threadIdx.x;
    const int tn = tid & 15;
    const int tm = tid >> 4;
    const int am = tid >> 2;
    const int ak = (tid & 3) << 2;
    const int wn = tid >> 2;

    float acc[4][8];
#pragma unroll
    for (int i = 0; i < 4; i++)
#pragma unroll
        for (int j = 0; j < 8; j++) acc[i][j] = 0.0f;

    const float* Ap  = A + (size_t)(m0 + am) * lda + kb + ak;
    const float* Wp0 = W + (size_t)(n0 + wn) * ldw + kb + ak;
    const float* Wp1 = Wp0 + (size_t)64 * ldw;

    for (int kk = 0; kk < Kc; kk += 16) {
        float4 av = *(const float4*)(Ap + kk);
        As[ak + 0][am] = av.x; As[ak + 1][am] = av.y;
        As[ak + 2][am] = av.z; As[ak + 3][am] = av.w;
        float4 w0 = *(const float4*)(Wp0 + kk);
        Ws[ak + 0][wn] = w0.x; Ws[ak + 1][wn] = w0.y;
        Ws[ak + 2][wn] = w0.z; Ws[ak + 3][wn] = w0.w;
        float4 w1 = *(const float4*)(Wp1 + kk);
        Ws[ak + 0][wn + 64] = w1.x; Ws[ak + 1][wn + 64] = w1.y;
        Ws[ak + 2][wn + 64] = w1.z; Ws[ak + 3][wn + 64] = w1.w;
        __syncthreads();
#pragma unroll
        for (int k = 0; k < 16; k++) {
            float4 a  = *(const float4*)&As[k][tm << 2];
            float4 b0 = *(const float4*)&Ws[k][tn << 3];
            float4 b1 = *(const float4*)&Ws[k][(tn << 3) + 4];
            float aa[4] = {a.x, a.y, a.z, a.w};
            float bb[8] = {b0.x, b0.y, b0.z, b0.w, b1.x, b1.y, b1.z, b1.w};
#pragma unroll
            for (int i = 0; i < 4; i++)
#pragma unroll
                for (int j = 0; j < 8; j++)
                    acc[i][j] = fmaf(aa[i], bb[j], acc[i][j]);
        }
        __syncthreads();
    }

    if (Cpart) {
        float* P = Cpart + (size_t)blockIdx.z * 64 * N;
#pragma unroll
        for (int i = 0; i < 4; i++) {
            int m = (tm << 2) + i;
#pragma unroll
            for (int j = 0; j < 8; j += 4) {
                int n = n0 + (tn << 3) + j;
                float4 o = {acc[i][j], acc[i][j + 1], acc[i][j + 2], acc[i][j + 3]};
                *(float4*)(P + (size_t)m * N + n) = o;
            }
        }
    } else {
#pragma unroll
        for (int i = 0; i < 4; i++) {
            int m = m0 + (tm << 2) + i;
#pragma unroll
            for (int j = 0; j < 8; j += 4) {
                int n = n0 + (tn << 3) + j;
                float4 o;
                o.x = acc[i][j + 0] + (bias ? bias[n + 0] : 0.0f);
                o.y = acc[i][j + 1] + (bias ? bias[n + 1] : 0.0f);
                o.z = acc[i][j + 2] + (bias ? bias[n + 2] : 0.0f);
                o.w = acc[i][j + 3] + (bias ? bias[n + 3] : 0.0f);
                *(float4*)(C + (size_t)m * ldc + n) = o;
            }
        }
    }
}

// Deterministic split-K reduction: C[m][n] = bias[n] + sum_z part[z][m][n]
__global__ void reduce_part_kernel(const float* __restrict__ part, int kz, int N,
                                   const float* __restrict__ bias,
                                   float* __restrict__ C, int ldc) {
    int i = blockIdx.x * blockDim.x + threadIdx.x;
    if (i >= 64 * N) return;
    int m = i / N, n = i % N;
    float s = bias ? bias[n] : 0.0f;
    for (int z = 0; z < kz; z++) s += part[(size_t)z * 64 * N + i];
    C[(size_t)m * ldc + n] = s;
}

// ---------------------------------------------------------------------------
// Fused attention step: one block per batch element.
// scores[s] = sum_h v[h] * tanh(q[b][h] + enc_proj[b][s][h])
// alpha = softmax(scores); ctx[d] = sum_s alpha[s] * enc[b][s][d]
// x[b] = [ emb[tok[b][t]] ; ctx ]
// ---------------------------------------------------------------------------
__global__ __launch_bounds__(256)
void attn_kernel(const float* __restrict__ ep,
                 const float* __restrict__ enc,
                 const float* __restrict__ q,
                 const float* __restrict__ vvec,
                 const float* __restrict__ emb,
                 const int* __restrict__ tok,
                 float* __restrict__ x,
                 int t) {
    const int b = blockIdx.x;
    __shared__ float sq[Hq];
    __shared__ float sv[Hq];
    __shared__ float sc[Sq];
    __shared__ float sred[8];
    const int tid = threadIdx.x;
    const int warp = tid >> 5, lane = tid & 31;

    for (int h = tid; h < Hq; h += 256) {
        sq[h] = q[b * Hq + h];
        sv[h] = vvec[h];
    }
    __syncthreads();

    // scores: one warp per source position
    for (int s = warp; s < Sq; s += 8) {
        const float* e = ep + (size_t)(b * Sq + s) * Hq;
        float sum = 0.0f;
        for (int h = lane; h < Hq; h += 32)
            sum += sv[h] * tanh_fast(sq[h] + e[h]);
#pragma unroll
        for (int o = 16; o > 0; o >>= 1)
            sum += __shfl_xor_sync(0xffffffffu, sum, o);
        if (lane == 0) sc[s] = sum;
    }
    __syncthreads();

    // softmax over S=128
    float vs = (tid < Sq) ? sc[tid] : -3.0e38f;
    float m = vs;
#pragma unroll
    for (int o = 16; o > 0; o >>= 1)
        m = fmaxf(m, __shfl_xor_sync(0xffffffffu, m, o));
    if (lane == 0) sred[warp] = m;
    __syncthreads();
    if (tid == 0) {
        float mm = sred[0];
        for (int i = 1; i < 8; i++) mm = fmaxf(mm, sred[i]);
        sred[0] = mm;
    }
    __syncthreads();
    const float mx = sred[0];
    float e1 = (tid < Sq) ? __expf(vs - mx) : 0.0f;
    float ssum = e1;
#pragma unroll
    for (int o = 16; o > 0; o >>= 1)
        ssum += __shfl_xor_sync(0xffffffffu, ssum, o);
    __syncthreads();
    if (lane == 0) sred[warp] = ssum;
    __syncthreads();
    if (tid == 0) {
        float tt = 0.0f;
        for (int i = 0; i < 8; i++) tt += sred[i];
        sred[0] = tt;
    }
    __syncthreads();
    const float inv = __fdividef(1.0f, sred[0]);
    if (tid < Sq) sc[tid] = e1 * inv;
    __syncthreads();

    // context -> x[b][E .. E+ENC)
    for (int d = tid; d < ENCq; d += 256) {
        const float* eb = enc + (size_t)b * Sq * ENCq + d;
        float sum = 0.0f;
#pragma unroll 4
        for (int s = 0; s < Sq; s++)
            sum += sc[s] * eb[(size_t)s * ENCq];
        x[b * KXq + Eq + d] = sum;
    }
    // embedding gather -> x[b][0 .. E)
    const int tk = tok[b * Tq + t];
    for (int e0 = tid; e0 < Eq; e0 += 256)
        x[b * KXq + e0] = emb[(size_t)tk * Eq + e0];
}

// ---------------------------------------------------------------------------
// GRU elementwise update
// ---------------------------------------------------------------------------
__global__ void gru_kernel(const float* __restrict__ gi,
                           const float* __restrict__ gh,
                           const float* __restrict__ hprev,
                           float* __restrict__ hnew) {
    int i = blockIdx.x * blockDim.x + threadIdx.x;  // B*H = 65536
    int b = i >> 10, j = i & 1023;
    const float* a = gi + b * G3q;
    const float* c = gh + b * G3q;
    float r = sigmoid_fast(a[j] + c[j]);
    float z = sigmoid_fast(a[Hq + j] + c[Hq + j]);
    float n = tanh_fast(a[2 * Hq + j] + r * c[2 * Hq + j]);
    hnew[i] = (1.0f - z) * n + z * hprev[i];
}

// ---------------------------------------------------------------------------
// Launch
// ---------------------------------------------------------------------------
extern "C" void kernel_launch(void* const* d_in, const int* in_sizes, int n_in,
                              void* d_out, int out_size) {
    const float* enc  = (const float*)d_in[0];   // [B,S,ENC]
    const float* h0in = (const float*)d_in[1];   // [1,B,H]
    const int*   tgt  = (const int*)d_in[2];     // [B,T] int64 or int32
    const float* emb  = (const float*)d_in[3];   // [V,E]
    const float* Wa   = (const float*)d_in[4];   // [H, H+ENC]
    const float* ba   = (const float*)d_in[5];   // [H]
    const float* vvec = (const float*)d_in[6];   // [H]
    const float* W_ih = (const float*)d_in[7];   // [3H, E+ENC]
    const float* b_ih = (const float*)d_in[8];   // [3H]
    const float* W_hh = (const float*)d_in[9];   // [3H, H]
    const float* b_hh = (const float*)d_in[10];  // [3H]
    const float* Wo   = (const float*)d_in[11];  // [V, H]
    const float* bo   = (const float*)d_in[12];  // [V]
    float* out = (float*)d_out;                  // [B, T, V]

    // Resolve device-global scratch addresses once (cached; lookup only, no
    // allocation, no stream work — capture-safe and deterministic).
    static float* scr = nullptr;
    static int* tokp = nullptr;
    if (!scr) {
        cudaGetSymbolAddress((void**)&scr, g_scr);
        cudaGetSymbolAddress((void**)&tokp, g_tok);
    }

    float* ep    = scr + OFF_EP;
    float* hbuf0 = scr + OFF_H0;
    float* hbuf1 = scr + OFF_H1;
    float* qp    = scr + OFF_Q;
    float* xp    = scr + OFF_X;
    float* gip   = scr + OFF_GI;
    float* ghp   = scr + OFF_GH;
    float* part  = scr + OFF_PART;

    prep_tokens_kernel<<<1, 256>>>(tgt, tokp);
    copy_kernel<<<(Bq * Hq + 255) / 256, 256>>>(h0in, hbuf0, Bq * Hq);

    // enc_proj: C[8192,1024] = enc[8192,2048] @ Wa_e[1024,2048]^T
    gemm64<<<dim3(Hq / 128, (Bq * Sq) / 64, 1), 256>>>(
        enc, ENCq, Wa + Hq, Hq + ENCq, nullptr, ep, Hq, nullptr, Hq, ENCq);

    for (int t = 0; t < Tq; t++) {
        float* hc = (t & 1) ? hbuf1 : hbuf0;
        float* hn = (t & 1) ? hbuf0 : hbuf1;

        // q = h @ Wa_q^T + ba   (N=1024, K=1024, split-K 16 x 64)
        gemm64<<<dim3(Hq / 128, 1, 16), 256>>>(
            hc, Hq, Wa, Hq + ENCq, nullptr, nullptr, 0, part, Hq, 64);
        reduce_part_kernel<<<(64 * Hq + 255) / 256, 256>>>(part, 16, Hq, ba, qp, Hq);

        // attention + embedding gather -> x
        attn_kernel<<<Bq, 256>>>(ep, enc, qp, vvec, emb, tokp, xp, t);

        // gi = x @ W_ih^T + b_ih  (N=3072, K=2560, split-K 8 x 320)
        gemm64<<<dim3(G3q / 128, 1, 8), 256>>>(
            xp, KXq, W_ih, KXq, nullptr, nullptr, 0, part, G3q, 320);
        reduce_part_kernel<<<(64 * G3q + 255) / 256, 256>>>(part, 8, G3q, b_ih, gip, G3q);

        // gh = h @ W_hh^T + b_hh  (N=3072, K=1024, split-K 8 x 128)
        gemm64<<<dim3(G3q / 128, 1, 8), 256>>>(
            hc, Hq, W_hh, Hq, nullptr, nullptr, 0, part, G3q, 128);
        reduce_part_kernel<<<(64 * G3q + 255) / 256, 256>>>(part, 8, G3q, b_hh, ghp, G3q);

        // GRU update
        gru_kernel<<<(Bq * Hq) / 256, 256>>>(gip, ghp, hc, hn);

        // logits: out[:, t, :] = h_new @ Wo^T + bo  (N=16000, K=1024, direct)
        gemm64<<<dim3(Vq / 128, 1, 1), 256>>>(
            hn, Hq, Wo, Hq, bo, out + (size_t)t * Vq, (long long)Tq * Vq, nullptr, Vq, Hq);
    }
}

// round 7
// speedup vs baseline: 1.0225x; 1.0225x over previous
#include <cuda_runtime.h>
#include <cuda_bf16.h>
#include <cstdint>

// Problem constants
#define Bq   64
#define Sq   128
#define Tq   64
#define Hq   1024
#define Eq   512
#define Vq   16000
#define ENCq 2048
#define KXq  (Eq + ENCq)   // 2560
#define G3q  (3 * Hq)      // 3072

// ===========================================================================
// Device-global scratch (runtime allocation is forbidden)
// ===========================================================================
__device__ __align__(16) float g_ep[Bq * Sq * Hq];        // enc_proj fp32
__device__ float g_h[2][Bq * Hq];                          // hidden fp32 ping-pong
__device__ __align__(16) __nv_bfloat16 g_hhi[2][Bq * Hq];
__device__ __align__(16) __nv_bfloat16 g_hlo[2][Bq * Hq];
__device__ float g_q[Bq * Hq];
__device__ __align__(16) __nv_bfloat16 g_xhi[Bq * KXq];
__device__ __align__(16) __nv_bfloat16 g_xlo[Bq * KXq];
__device__ float g_gi[Bq * G3q];
__device__ float g_gh[Bq * G3q];
__device__ __align__(16) __nv_bfloat16 g_Wohi[Vq * Hq];
__device__ __align__(16) __nv_bfloat16 g_Wolo[Vq * Hq];
__device__ __align__(16) __nv_bfloat16 g_Wihhi[G3q * KXq];
__device__ __align__(16) __nv_bfloat16 g_Wihlo[G3q * KXq];
__device__ __align__(16) __nv_bfloat16 g_Whhhi[G3q * Hq];
__device__ __align__(16) __nv_bfloat16 g_Whhlo[G3q * Hq];
__device__ __align__(16) __nv_bfloat16 g_Waqhi[Hq * Hq];
__device__ __align__(16) __nv_bfloat16 g_Waqlo[Hq * Hq];
__device__ __align__(16) __nv_bfloat16 g_Waehi[Hq * ENCq];
__device__ __align__(16) __nv_bfloat16 g_Waelo[Hq * ENCq];
__device__ __align__(16) __nv_bfloat16 g_enchi[Bq * Sq * ENCq];
__device__ __align__(16) __nv_bfloat16 g_enclo[Bq * Sq * ENCq];
__device__ int g_tok[Bq * Tq];

// ===========================================================================
// Fast math helpers
// ===========================================================================
__device__ __forceinline__ float tanh_fast(float x) {
    float e = __expf(2.0f * x);
    return 1.0f - __fdividef(2.0f, e + 1.0f);
}
__device__ __forceinline__ float sigmoid_fast(float x) {
    return __fdividef(1.0f, 1.0f + __expf(-x));
}
__device__ __forceinline__ void split_bf16(float x, __nv_bfloat16* hi, __nv_bfloat16* lo) {
    __nv_bfloat16 h = __float2bfloat16(x);
    *hi = h;
    *lo = __float2bfloat16(x - __bfloat162float(h));
}

// ===========================================================================
// Token prep (int64/int32 autodetect) + misc elementwise kernels
// ===========================================================================
__global__ void prep_tokens_kernel(const int* __restrict__ tgt_raw,
                                   int* __restrict__ tok) {
    __shared__ int s_nonzero;
    if (threadIdx.x == 0) s_nonzero = 0;
    __syncthreads();
    int c = 0;
    for (int i = threadIdx.x; i < (Bq * Tq) / 2; i += blockDim.x)
        if (tgt_raw[2 * i + 1] != 0) c++;
    if (c) atomicAdd(&s_nonzero, c);
    __syncthreads();
    const bool is64 = (s_nonzero == 0);
    const long long* tgt64 = (const long long*)tgt_raw;
    for (int i = threadIdx.x; i < Bq * Tq; i += blockDim.x) {
        int b = i / Tq, t = i % Tq;
        int val;
        if (t == 0) val = 1;  // SOS
        else {
            int src = b * Tq + (t - 1);
            val = is64 ? (int)tgt64[src] : tgt_raw[src];
        }
        tok[i] = val;
    }
}

__global__ void copy_kernel(const float* __restrict__ src,
                            float* __restrict__ dst, int n) {
    int i = blockIdx.x * blockDim.x + threadIdx.x;
    if (i < n) dst[i] = src[i];
}

// Split fp32 (strided rows / column offset) into hi/lo bf16 packed arrays
__global__ void split_kernel(const float* __restrict__ src, int rowStride,
                             int cols, int colOff,
                             __nv_bfloat16* __restrict__ hi,
                             __nv_bfloat16* __restrict__ lo, int total) {
    int i = blockIdx.x * blockDim.x + threadIdx.x;
    if (i >= total) return;
    int r = i / cols, c = i % cols;
    float x = src[(size_t)r * rowStride + colOff + c];
    __nv_bfloat16 h, l;
    split_bf16(x, &h, &l);
    hi[i] = h;
    lo[i] = l;
}

// ===========================================================================
// mma.sync bf16x3 GEMM:
//   out[(a0+m)*ldout + n] = bias[n] + sum_k W[n][k] * A[m][k]
// computed as Whi*Ahi + Whi*Alo + Wlo*Ahi with fp32 accumulators.
// Block: 64 activation rows (grid.y) x 128 weight rows (grid.x), BK=32.
// 256 threads = 8 warps in 2(m) x 4(n); warp tile 32x32 = 2x4 m16n8k16.
// K must be a multiple of 32. All dims exact tile multiples.
// ===========================================================================
#define RS 40   // smem row stride in bf16 elements (20 words: conflict-free)

__device__ __forceinline__ void mma_bf16(float c[4], const uint32_t a[4],
                                         const uint32_t b[2]) {
    asm volatile(
        "mma.sync.aligned.m16n8k16.row.col.f32.bf16.bf16.f32 "
        "{%0,%1,%2,%3}, {%4,%5,%6,%7}, {%8,%9}, {%0,%1,%2,%3};"
        : "+f"(c[0]), "+f"(c[1]), "+f"(c[2]), "+f"(c[3])
        : "r"(a[0]), "r"(a[1]), "r"(a[2]), "r"(a[3]), "r"(b[0]), "r"(b[1]));
}

__device__ __forceinline__ void ldfragA(uint32_t f[4], const __nv_bfloat16* t,
                                        int row, int k, int g, int tg) {
    f[0] = *(const uint32_t*)&t[(row + g) * RS + k + 2 * tg];
    f[1] = *(const uint32_t*)&t[(row + g + 8) * RS + k + 2 * tg];
    f[2] = *(const uint32_t*)&t[(row + g) * RS + k + 8 + 2 * tg];
    f[3] = *(const uint32_t*)&t[(row + g + 8) * RS + k + 8 + 2 * tg];
}
__device__ __forceinline__ void ldfragB(uint32_t f[2], const __nv_bfloat16* t,
                                        int nrow, int k, int g, int tg) {
    f[0] = *(const uint32_t*)&t[(nrow + g) * RS + k + 2 * tg];
    f[1] = *(const uint32_t*)&t[(nrow + g) * RS + k + 8 + 2 * tg];
}

__global__ __launch_bounds__(256)
void gemm_mma(const __nv_bfloat16* __restrict__ Whi,
              const __nv_bfloat16* __restrict__ Wlo,
              const __nv_bfloat16* __restrict__ Ahi,
              const __nv_bfloat16* __restrict__ Alo,
              const float* __restrict__ bias,
              float* __restrict__ out, long long ldout,
              int K) {
    __shared__ __nv_bfloat16 sWhi[128 * RS];
    __shared__ __nv_bfloat16 sWlo[128 * RS];
    __shared__ __nv_bfloat16 sAhi[64 * RS];
    __shared__ __nv_bfloat16 sAlo[64 * RS];

    const int tid = threadIdx.x;
    const int wid = tid >> 5, lane = tid & 31;
    const int wm = wid >> 2;       // 0..1 : m half
    const int wn = wid & 3;        // 0..3 : n quarter
    const int g = lane >> 2;       // group 0..7
    const int tg = lane & 3;       // thread-in-group
    const int n0 = blockIdx.x * 128;
    const int a0 = blockIdx.y * 64;

    float acc[2][4][4];
#pragma unroll
    for (int i = 0; i < 2; i++)
#pragma unroll
        for (int j = 0; j < 4; j++)
#pragma unroll
            for (int r = 0; r < 4; r++) acc[i][j][r] = 0.0f;

    const int wrow = tid >> 2, wseg = tid & 3;   // W loads: 256 of 512 pairs
    const int arow = tid >> 2, aseg = tid & 3;   // A loads: exactly 256

    for (int kb = 0; kb < K; kb += 32) {
        // Load W tile: 128 rows x 32 bf16 (hi+lo)
#pragma unroll
        for (int i = 0; i < 2; i++) {
            int row = wrow + i * 64;
            const size_t gsrc = (size_t)(n0 + row) * K + kb + wseg * 8;
            *(uint4*)&sWhi[row * RS + wseg * 8] = *(const uint4*)(Whi + gsrc);
            *(uint4*)&sWlo[row * RS + wseg * 8] = *(const uint4*)(Wlo + gsrc);
        }
        // Load A tile: 64 rows x 32 bf16 (hi+lo)
        {
            const size_t gsrc = (size_t)(a0 + arow) * K + kb + aseg * 8;
            *(uint4*)&sAhi[arow * RS + aseg * 8] = *(const uint4*)(Ahi + gsrc);
            *(uint4*)&sAlo[arow * RS + aseg * 8] = *(const uint4*)(Alo + gsrc);
        }
        __syncthreads();

#pragma unroll
        for (int kk = 0; kk < 32; kk += 16) {
            uint32_t ahi[2][4], alo[2][4];
#pragma unroll
            for (int tm = 0; tm < 2; tm++) {
                ldfragA(ahi[tm], sAhi, wm * 32 + tm * 16, kk, g, tg);
                ldfragA(alo[tm], sAlo, wm * 32 + tm * 16, kk, g, tg);
            }
            uint32_t bhi[4][2], blo[4][2];
#pragma unroll
            for (int tn = 0; tn < 4; tn++) {
                ldfragB(bhi[tn], sWhi, wn * 32 + tn * 8, kk, g, tg);
                ldfragB(blo[tn], sWlo, wn * 32 + tn * 8, kk, g, tg);
            }
#pragma unroll
            for (int tm = 0; tm < 2; tm++)
#pragma unroll
                for (int tn = 0; tn < 4; tn++) {
                    mma_bf16(acc[tm][tn], ahi[tm], bhi[tn]);
                    mma_bf16(acc[tm][tn], ahi[tm], blo[tn]);
                    mma_bf16(acc[tm][tn], alo[tm], bhi[tn]);
                }
        }
        __syncthreads();
    }

    // Epilogue: acc rows -> activations (m), cols -> weight rows (n)
#pragma unroll
    for (int tm = 0; tm < 2; tm++) {
#pragma unroll
        for (int tn = 0; tn < 4; tn++) {
            const int mr = a0 + wm * 32 + tm * 16 + g;
            const int nc = n0 + wn * 32 + tn * 8 + 2 * tg;
            const float b0v = bias ? bias[nc] : 0.0f;
            const float b1v = bias ? bias[nc + 1] : 0.0f;
            float2 o0 = {acc[tm][tn][0] + b0v, acc[tm][tn][1] + b1v};
            float2 o1 = {acc[tm][tn][2] + b0v, acc[tm][tn][3] + b1v};
            *(float2*)(out + (size_t)mr * ldout + nc) = o0;
            *(float2*)(out + (size_t)(mr + 8) * ldout + nc) = o1;
        }
    }
}

// ===========================================================================
// Fused attention step: one block per batch element.
// ===========================================================================
__global__ __launch_bounds__(256)
void attn_kernel(const float* __restrict__ ep,
                 const float* __restrict__ enc,
                 const float* __restrict__ q,
                 const float* __restrict__ vvec,
                 const float* __restrict__ emb,
                 const int* __restrict__ tok,
                 __nv_bfloat16* __restrict__ xhi,
                 __nv_bfloat16* __restrict__ xlo,
                 int t) {
    const int b = blockIdx.x;
    __shared__ float sq[Hq];
    __shared__ float sv[Hq];
    __shared__ float sc[Sq];
    __shared__ float sred[8];
    const int tid = threadIdx.x;
    const int warp = tid >> 5, lane = tid & 31;

    for (int h = tid; h < Hq; h += 256) {
        sq[h] = q[b * Hq + h];
        sv[h] = vvec[h];
    }
    __syncthreads();

    for (int s = warp; s < Sq; s += 8) {
        const float* e = ep + (size_t)(b * Sq + s) * Hq;
        float sum = 0.0f;
        for (int h = lane; h < Hq; h += 32)
            sum += sv[h] * tanh_fast(sq[h] + e[h]);
#pragma unroll
        for (int o = 16; o > 0; o >>= 1)
            sum += __shfl_xor_sync(0xffffffffu, sum, o);
        if (lane == 0) sc[s] = sum;
    }
    __syncthreads();

    // softmax over S=128
    float vs = (tid < Sq) ? sc[tid] : -3.0e38f;
    float m = vs;
#pragma unroll
    for (int o = 16; o > 0; o >>= 1)
        m = fmaxf(m, __shfl_xor_sync(0xffffffffu, m, o));
    if (lane == 0) sred[warp] = m;
    __syncthreads();
    if (tid == 0) {
        float mm = sred[0];
        for (int i = 1; i < 8; i++) mm = fmaxf(mm, sred[i]);
        sred[0] = mm;
    }
    __syncthreads();
    const float mx = sred[0];
    float e1 = (tid < Sq) ? __expf(vs - mx) : 0.0f;
    float ssum = e1;
#pragma unroll
    for (int o = 16; o > 0; o >>= 1)
        ssum += __shfl_xor_sync(0xffffffffu, ssum, o);
    __syncthreads();
    if (lane == 0) sred[warp] = ssum;
    __syncthreads();
    if (tid == 0) {
        float tt = 0.0f;
        for (int i = 0; i < 8; i++) tt += sred[i];
        sred[0] = tt;
    }
    __syncthreads();
    const float inv = __fdividef(1.0f, sred[0]);
    if (tid < Sq) sc[tid] = e1 * inv;
    __syncthreads();

    // context -> x[b][E..E+ENC)
    for (int d = tid; d < ENCq; d += 256) {
        const float* eb = enc + (size_t)b * Sq * ENCq + d;
        float sum = 0.0f;
#pragma unroll 4
        for (int s = 0; s < Sq; s++)
            sum += sc[s] * eb[(size_t)s * ENCq];
        __nv_bfloat16 h, l;
        split_bf16(sum, &h, &l);
        xhi[b * KXq + Eq + d] = h;
        xlo[b * KXq + Eq + d] = l;
    }
    // embedding gather -> x[b][0..E)
    const int tk = tok[b * Tq + t];
    for (int e0 = tid; e0 < Eq; e0 += 256) {
        float v = emb[(size_t)tk * Eq + e0];
        __nv_bfloat16 h, l;
        split_bf16(v, &h, &l);
        xhi[b * KXq + e0] = h;
        xlo[b * KXq + e0] = l;
    }
}

// ===========================================================================
// GRU elementwise update (+ write hi/lo split of h_new)
// ===========================================================================
__global__ void gru_kernel(const float* __restrict__ gi,
                           const float* __restrict__ gh,
                           const float* __restrict__ hprev,
                           float* __restrict__ hnew,
                           __nv_bfloat16* __restrict__ hhi,
                           __nv_bfloat16* __restrict__ hlo) {
    int i = blockIdx.x * blockDim.x + threadIdx.x;  // B*H = 65536
    int b = i >> 10, j = i & 1023;
    const float* a = gi + b * G3q;
    const float* c = gh + b * G3q;
    float r = sigmoid_fast(a[j] + c[j]);
    float z = sigmoid_fast(a[Hq + j] + c[Hq + j]);
    float n = tanh_fast(a[2 * Hq + j] + r * c[2 * Hq + j]);
    float hv = (1.0f - z) * n + z * hprev[i];
    hnew[i] = hv;
    __nv_bfloat16 h, l;
    split_bf16(hv, &h, &l);
    hhi[i] = h;
    hlo[i] = l;
}

// ===========================================================================
// Launch
// ===========================================================================
extern "C" void kernel_launch(void* const* d_in, const int* in_sizes, int n_in,
                              void* d_out, int out_size) {
    const float* enc  = (const float*)d_in[0];   // [B,S,ENC]
    const float* h0in = (const float*)d_in[1];   // [1,B,H]
    const int*   tgt  = (const int*)d_in[2];     // [B,T]
    const float* emb  = (const float*)d_in[3];   // [V,E]
    const float* Wa   = (const float*)d_in[4];   // [H, H+ENC]
    const float* ba   = (const float*)d_in[5];   // [H]
    const float* vvec = (const float*)d_in[6];   // [H]
    const float* W_ih = (const float*)d_in[7];   // [3H, E+ENC]
    const float* b_ih = (const float*)d_in[8];   // [3H]
    const float* W_hh = (const float*)d_in[9];   // [3H, H]
    const float* b_hh = (const float*)d_in[10];  // [3H]
    const float* Wo   = (const float*)d_in[11];  // [V, H]
    const float* bo   = (const float*)d_in[12];  // [V]
    float* out = (float*)d_out;                  // [B, T, V]

    // Resolve device-global addresses once (lookup only; capture-safe)
    static bool init_done = false;
    static float *ep, *h0b, *h1b, *qp, *gip, *ghp;
    static __nv_bfloat16 *hhi0, *hhi1, *hlo0, *hlo1, *xhi, *xlo;
    static __nv_bfloat16 *Wohi, *Wolo, *Wihhi, *Wihlo, *Whhhi, *Whhlo;
    static __nv_bfloat16 *Waqhi, *Waqlo, *Waehi, *Waelo, *enchi, *enclo;
    static int* tokp;
    if (!init_done) {
        cudaGetSymbolAddress((void**)&ep, g_ep);
        void* p;
        cudaGetSymbolAddress(&p, g_h);    h0b = (float*)p; h1b = h0b + Bq * Hq;
        cudaGetSymbolAddress(&p, g_hhi);  hhi0 = (__nv_bfloat16*)p; hhi1 = hhi0 + Bq * Hq;
        cudaGetSymbolAddress(&p, g_hlo);  hlo0 = (__nv_bfloat16*)p; hlo1 = hlo0 + Bq * Hq;
        cudaGetSymbolAddress((void**)&qp, g_q);
        cudaGetSymbolAddress((void**)&xhi, g_xhi);
        cudaGetSymbolAddress((void**)&xlo, g_xlo);
        cudaGetSymbolAddress((void**)&gip, g_gi);
        cudaGetSymbolAddress((void**)&ghp, g_gh);
        cudaGetSymbolAddress((void**)&Wohi, g_Wohi);
        cudaGetSymbolAddress((void**)&Wolo, g_Wolo);
        cudaGetSymbolAddress((void**)&Wihhi, g_Wihhi);
        cudaGetSymbolAddress((void**)&Wihlo, g_Wihlo);
        cudaGetSymbolAddress((void**)&Whhhi, g_Whhhi);
        cudaGetSymbolAddress((void**)&Whhlo, g_Whhlo);
        cudaGetSymbolAddress((void**)&Waqhi, g_Waqhi);
        cudaGetSymbolAddress((void**)&Waqlo, g_Waqlo);
        cudaGetSymbolAddress((void**)&Waehi, g_Waehi);
        cudaGetSymbolAddress((void**)&Waelo, g_Waelo);
        cudaGetSymbolAddress((void**)&enchi, g_enchi);
        cudaGetSymbolAddress((void**)&enclo, g_enclo);
        cudaGetSymbolAddress((void**)&tokp, g_tok);
        init_done = true;
    }

    prep_tokens_kernel<<<1, 256>>>(tgt, tokp);
    copy_kernel<<<(Bq * Hq + 255) / 256, 256>>>(h0in, h0b, Bq * Hq);
    split_kernel<<<(Bq * Hq + 255) / 256, 256>>>(h0in, Hq, Hq, 0, hhi0, hlo0, Bq * Hq);

    // Weight / encoder splits (constant across the run; recomputed each call)
    split_kernel<<<(Vq * Hq + 255) / 256, 256>>>(Wo, Hq, Hq, 0, Wohi, Wolo, Vq * Hq);
    split_kernel<<<(G3q * KXq + 255) / 256, 256>>>(W_ih, KXq, KXq, 0, Wihhi, Wihlo, G3q * KXq);
    split_kernel<<<(G3q * Hq + 255) / 256, 256>>>(W_hh, Hq, Hq, 0, Whhhi, Whhlo, G3q * Hq);
    split_kernel<<<(Hq * Hq + 255) / 256, 256>>>(Wa, Hq + ENCq, Hq, 0, Waqhi, Waqlo, Hq * Hq);
    split_kernel<<<(Hq * ENCq + 255) / 256, 256>>>(Wa, Hq + ENCq, ENCq, Hq, Waehi, Waelo, Hq * ENCq);
    split_kernel<<<(Bq * Sq * ENCq + 255) / 256, 256>>>(enc, ENCq, ENCq, 0, enchi, enclo, Bq * Sq * ENCq);

    // enc_proj: ep[pos*H + h] = enc[pos]·Wa_e[h]   (N=1024, Mact=8192, K=2048)
    gemm_mma<<<dim3(Hq / 128, (Bq * Sq) / 64), 256>>>(
        Waehi, Waelo, enchi, enclo, nullptr, ep, Hq, ENCq);

    for (int t = 0; t < Tq; t++) {
        __nv_bfloat16* chi = (t & 1) ? hhi1 : hhi0;
        __nv_bfloat16* clo = (t & 1) ? hlo1 : hlo0;
        __nv_bfloat16* nhi = (t & 1) ? hhi0 : hhi1;
        __nv_bfloat16* nlo = (t & 1) ? hlo0 : hlo1;
        float* hc = (t & 1) ? h1b : h0b;
        float* hn = (t & 1) ? h0b : h1b;

        // q = h @ Wa_q^T + ba   (N=1024, K=1024)
        gemm_mma<<<dim3(Hq / 128, 1), 256>>>(
            Waqhi, Waqlo, chi, clo, ba, qp, Hq, Hq);

        // attention + embedding gather -> x (hi/lo)
        attn_kernel<<<Bq, 256>>>(ep, enc, qp, vvec, emb, tokp, xhi, xlo, t);

        // gi = x @ W_ih^T + b_ih  (N=3072, K=2560)
        gemm_mma<<<dim3(G3q / 128, 1), 256>>>(
            Wihhi, Wihlo, xhi, xlo, b_ih, gip, G3q, KXq);

        // gh = h @ W_hh^T + b_hh  (N=3072, K=1024)
        gemm_mma<<<dim3(G3q / 128, 1), 256>>>(
            Whhhi, Whhlo, chi, clo, b_hh, ghp, G3q, Hq);

        // GRU update (+ split of h_new)
        gru_kernel<<<(Bq * Hq) / 256, 256>>>(gip, ghp, hc, hn, nhi, nlo);

        // logits: out[:, t, :] = h_new @ Wo^T + bo  (N=16000, K=1024)
        gemm_mma<<<dim3(Vq / 128, 1), 256>>>(
            Wohi, Wolo, nhi, nlo, bo, out + (size_t)t * Vq, (long long)Tq * Vq, Hq);
    }
}

// round 8
// speedup vs baseline: 2.6931x; 2.6338x over previous
#include <cuda_runtime.h>
#include <cuda_bf16.h>
#include <cstdint>

// Problem constants
#define Bq   64
#define Sq   128
#define Tq   64
#define Hq   1024
#define Eq   512
#define Vq   16000
#define ENCq 2048
#define KXq  (Eq + ENCq)   // 2560
#define G3q  (3 * Hq)      // 3072

// ===========================================================================
// Device-global scratch (runtime allocation is forbidden)
// ===========================================================================
__device__ __align__(16) float g_ep[Bq * Sq * Hq];        // enc_proj fp32
__device__ float g_h[2][Bq * Hq];                          // hidden fp32 ping-pong
__device__ __align__(16) __nv_bfloat16 g_hhi[2][Bq * Hq];
__device__ __align__(16) __nv_bfloat16 g_hlo[2][Bq * Hq];
__device__ float g_q[Bq * Hq];
__device__ float g_scores[Bq * Sq];
__device__ __align__(16) __nv_bfloat16 g_xhi[Bq * KXq];
__device__ __align__(16) __nv_bfloat16 g_xlo[Bq * KXq];
__device__ float g_gi[Bq * G3q];
__device__ float g_gh[Bq * G3q];
__device__ __align__(16) __nv_bfloat16 g_Wohi[Vq * Hq];
__device__ __align__(16) __nv_bfloat16 g_Wolo[Vq * Hq];
__device__ __align__(16) __nv_bfloat16 g_Wihhi[G3q * KXq];
__device__ __align__(16) __nv_bfloat16 g_Wihlo[G3q * KXq];
__device__ __align__(16) __nv_bfloat16 g_Whhhi[G3q * Hq];
__device__ __align__(16) __nv_bfloat16 g_Whhlo[G3q * Hq];
__device__ __align__(16) __nv_bfloat16 g_Waqhi[Hq * Hq];
__device__ __align__(16) __nv_bfloat16 g_Waqlo[Hq * Hq];
__device__ __align__(16) __nv_bfloat16 g_Waehi[Hq * ENCq];
__device__ __align__(16) __nv_bfloat16 g_Waelo[Hq * ENCq];
__device__ __align__(16) __nv_bfloat16 g_enchi[Bq * Sq * ENCq];
__device__ __align__(16) __nv_bfloat16 g_enclo[Bq * Sq * ENCq];
__device__ int g_tok[Bq * Tq];

// ===========================================================================
// Helpers
// ===========================================================================
__device__ __forceinline__ float tanh_fast(float x) {
    float e = __expf(2.0f * x);
    return 1.0f - __fdividef(2.0f, e + 1.0f);
}
__device__ __forceinline__ float sigmoid_fast(float x) {
    return __fdividef(1.0f, 1.0f + __expf(-x));
}
__device__ __forceinline__ void split_bf16(float x, __nv_bfloat16* hi, __nv_bfloat16* lo) {
    __nv_bfloat16 h = __float2bfloat16(x);
    *hi = h;
    *lo = __float2bfloat16(x - __bfloat162float(h));
}
__device__ __forceinline__ void cp16(void* smem_dst, const void* gsrc) {
    uint32_t s = (uint32_t)__cvta_generic_to_shared(smem_dst);
    asm volatile("cp.async.cg.shared.global [%0], [%1], 16;" :: "r"(s), "l"(gsrc));
}
__device__ __forceinline__ void cp_commit() {
    asm volatile("cp.async.commit_group;" ::: "memory");
}
template <int N>
__device__ __forceinline__ void cp_wait() {
    asm volatile("cp.async.wait_group %0;" :: "n"(N) : "memory");
}

// ===========================================================================
// Token prep + misc elementwise kernels
// ===========================================================================
__global__ void prep_tokens_kernel(const int* __restrict__ tgt_raw,
                                   int* __restrict__ tok) {
    __shared__ int s_nonzero;
    if (threadIdx.x == 0) s_nonzero = 0;
    __syncthreads();
    int c = 0;
    for (int i = threadIdx.x; i < (Bq * Tq) / 2; i += blockDim.x)
        if (tgt_raw[2 * i + 1] != 0) c++;
    if (c) atomicAdd(&s_nonzero, c);
    __syncthreads();
    const bool is64 = (s_nonzero == 0);
    const long long* tgt64 = (const long long*)tgt_raw;
    for (int i = threadIdx.x; i < Bq * Tq; i += blockDim.x) {
        int b = i / Tq, t = i % Tq;
        int val;
        if (t == 0) val = 1;  // SOS
        else {
            int src = b * Tq + (t - 1);
            val = is64 ? (int)tgt64[src] : tgt_raw[src];
        }
        tok[i] = val;
    }
}

__global__ void copy_kernel(const float* __restrict__ src,
                            float* __restrict__ dst, int n) {
    int i = blockIdx.x * blockDim.x + threadIdx.x;
    if (i < n) dst[i] = src[i];
}

__global__ void split_kernel(const float* __restrict__ src, int rowStride,
                             int cols, int colOff,
                             __nv_bfloat16* __restrict__ hi,
                             __nv_bfloat16* __restrict__ lo, int total) {
    int i = blockIdx.x * blockDim.x + threadIdx.x;
    if (i >= total) return;
    int r = i / cols, c = i % cols;
    float x = src[(size_t)r * rowStride + colOff + c];
    __nv_bfloat16 h, l;
    split_bf16(x, &h, &l);
    hi[i] = h;
    lo[i] = l;
}

// ===========================================================================
// Pipelined mma.sync bf16x3 GEMM (cp.async double-buffered, BK=64).
//   out[(a0+m)*ld + n] = bias[n] + sum_k W[n][k] * A[m][k]
// products: Whi*Ahi + Whi*Alo + Wlo*Ahi, fp32 accumulators.
// Supports a fused 2-matrix mode: weight rows [0,n1) come from W1 -> out1,
// rows [n1,..) from W2 -> out2 (n1 must be a multiple of 128).
// Block: 64 act rows x 128 weight rows; 256 thr = 8 warps (2m x 4n),
// warp tile 32x32 = 2x4 m16n8k16, 3 products each.
// K must be a multiple of 64.
// ===========================================================================
#define BK 64
#define RS 72                      // smem row stride (bf16): conflict-free
#define STAGE_ELEMS (384 * RS)     // Whi(128)+Wlo(128)+Ahi(64)+Alo(64) rows
#define GEMM_SMEM_BYTES (2 * STAGE_ELEMS * 2)

__device__ __forceinline__ void mma_bf16(float c[4], const uint32_t a[4],
                                         const uint32_t b[2]) {
    asm volatile(
        "mma.sync.aligned.m16n8k16.row.col.f32.bf16.bf16.f32 "
        "{%0,%1,%2,%3}, {%4,%5,%6,%7}, {%8,%9}, {%0,%1,%2,%3};"
        : "+f"(c[0]), "+f"(c[1]), "+f"(c[2]), "+f"(c[3])
        : "r"(a[0]), "r"(a[1]), "r"(a[2]), "r"(a[3]), "r"(b[0]), "r"(b[1]));
}
__device__ __forceinline__ void ldfragA(uint32_t f[4], const __nv_bfloat16* t,
                                        int row, int k, int g, int tg) {
    f[0] = *(const uint32_t*)&t[(row + g) * RS + k + 2 * tg];
    f[1] = *(const uint32_t*)&t[(row + g + 8) * RS + k + 2 * tg];
    f[2] = *(const uint32_t*)&t[(row + g) * RS + k + 8 + 2 * tg];
    f[3] = *(const uint32_t*)&t[(row + g + 8) * RS + k + 8 + 2 * tg];
}
__device__ __forceinline__ void ldfragB(uint32_t f[2], const __nv_bfloat16* t,
                                        int nrow, int k, int g, int tg) {
    f[0] = *(const uint32_t*)&t[(nrow + g) * RS + k + 2 * tg];
    f[1] = *(const uint32_t*)&t[(nrow + g) * RS + k + 8 + 2 * tg];
}

__global__ __launch_bounds__(256)
void gemm_mma2(const __nv_bfloat16* __restrict__ W1hi,
               const __nv_bfloat16* __restrict__ W1lo, int n1,
               const __nv_bfloat16* __restrict__ W2hi,
               const __nv_bfloat16* __restrict__ W2lo,
               const float* __restrict__ bias1, const float* __restrict__ bias2,
               float* __restrict__ out1, long long ld1,
               float* __restrict__ out2, long long ld2,
               const __nv_bfloat16* __restrict__ Ahi,
               const __nv_bfloat16* __restrict__ Alo,
               int K) {
    extern __shared__ __nv_bfloat16 dsm[];
    const int tid = threadIdx.x;
    const int wid = tid >> 5, lane = tid & 31;
    const int wm = wid >> 2, wn = wid & 3;
    const int g = lane >> 2, tg = lane & 3;
    const int n0 = blockIdx.x * 128;
    const int a0 = blockIdx.y * 64;

    // Select which weight matrix / output this block belongs to
    const bool first = (n0 < n1);
    const __nv_bfloat16* Whi = first ? W1hi + (size_t)n0 * K
                                     : W2hi + (size_t)(n0 - n1) * K;
    const __nv_bfloat16* Wlo = first ? W1lo + (size_t)n0 * K
                                     : W2lo + (size_t)(n0 - n1) * K;
    const float* bias = first ? bias1 : bias2;
    float* outp = first ? out1 : out2;
    const long long ld = first ? ld1 : ld2;
    const int nloc = first ? n0 : (n0 - n1);

    float acc[2][4][4];
#pragma unroll
    for (int i = 0; i < 2; i++)
#pragma unroll
        for (int j = 0; j < 4; j++)
#pragma unroll
            for (int r = 0; r < 4; r++) acc[i][j][r] = 0.0f;

    const int lrow = tid >> 3, lseg = tid & 7;  // load mapping: 8 segs/row
    const int nc = K / BK;

    // ---- stage issue ----
    auto issue = [&](int c, int st) {
        const int kb = c * BK;
        __nv_bfloat16* base = dsm + st * STAGE_ELEMS;
        __nv_bfloat16* sWhi = base;
        __nv_bfloat16* sWlo = base + 128 * RS;
        __nv_bfloat16* sAhi = base + 256 * RS;
        __nv_bfloat16* sAlo = base + 320 * RS;
#pragma unroll
        for (int i = 0; i < 4; i++) {
            int row = lrow + i * 32;   // 0..127
            cp16(sWhi + row * RS + lseg * 8, Whi + (size_t)row * K + kb + lseg * 8);
            cp16(sWlo + row * RS + lseg * 8, Wlo + (size_t)row * K + kb + lseg * 8);
        }
#pragma unroll
        for (int i = 0; i < 2; i++) {
            int row = lrow + i * 32;   // 0..63
            cp16(sAhi + row * RS + lseg * 8, Ahi + (size_t)(a0 + row) * K + kb + lseg * 8);
            cp16(sAlo + row * RS + lseg * 8, Alo + (size_t)(a0 + row) * K + kb + lseg * 8);
        }
        cp_commit();
    };

    issue(0, 0);
    for (int c = 0; c < nc; c++) {
        if (c + 1 < nc) {
            issue(c + 1, (c + 1) & 1);
            cp_wait<1>();
        } else {
            cp_wait<0>();
        }
        __syncthreads();

        const __nv_bfloat16* base = dsm + (c & 1) * STAGE_ELEMS;
        const __nv_bfloat16* sWhi = base;
        const __nv_bfloat16* sWlo = base + 128 * RS;
        const __nv_bfloat16* sAhi = base + 256 * RS;
        const __nv_bfloat16* sAlo = base + 320 * RS;

#pragma unroll
        for (int kk = 0; kk < BK; kk += 16) {
            uint32_t ahi[2][4], alo[2][4];
#pragma unroll
            for (int tm = 0; tm < 2; tm++) {
                ldfragA(ahi[tm], sAhi, wm * 32 + tm * 16, kk, g, tg);
                ldfragA(alo[tm], sAlo, wm * 32 + tm * 16, kk, g, tg);
            }
            uint32_t bhi[4][2], blo[4][2];
#pragma unroll
            for (int tn = 0; tn < 4; tn++) {
                ldfragB(bhi[tn], sWhi, wn * 32 + tn * 8, kk, g, tg);
                ldfragB(blo[tn], sWlo, wn * 32 + tn * 8, kk, g, tg);
            }
#pragma unroll
            for (int tm = 0; tm < 2; tm++)
#pragma unroll
                for (int tn = 0; tn < 4; tn++) {
                    mma_bf16(acc[tm][tn], ahi[tm], bhi[tn]);
                    mma_bf16(acc[tm][tn], ahi[tm], blo[tn]);
                    mma_bf16(acc[tm][tn], alo[tm], bhi[tn]);
                }
        }
        __syncthreads();
    }

    // Epilogue
#pragma unroll
    for (int tm = 0; tm < 2; tm++) {
#pragma unroll
        for (int tn = 0; tn < 4; tn++) {
            const int mr = a0 + wm * 32 + tm * 16 + g;
            const int nc2 = nloc + wn * 32 + tn * 8 + 2 * tg;
            const float b0v = bias ? bias[nc2] : 0.0f;
            const float b1v = bias ? bias[nc2 + 1] : 0.0f;
            float2 o0 = {acc[tm][tn][0] + b0v, acc[tm][tn][1] + b1v};
            float2 o1 = {acc[tm][tn][2] + b0v, acc[tm][tn][3] + b1v};
            *(float2*)(outp + (size_t)mr * ld + nc2) = o0;
            *(float2*)(outp + (size_t)(mr + 8) * ld + nc2) = o1;
        }
    }
}

// ===========================================================================
// Attention scores: grid (B, 4); block handles 32 s-positions.
// scores[b][s] = sum_h v[h] * tanh(q[b][h] + ep[b][s][h])
// ===========================================================================
__global__ __launch_bounds__(256)
void attn_scores_kernel(const float* __restrict__ ep,
                        const float* __restrict__ q,
                        const float* __restrict__ vvec,
                        float* __restrict__ scores) {
    const int b = blockIdx.x;
    const int chunk = blockIdx.y;   // 0..3
    __shared__ float sq[Hq];
    __shared__ float sv[Hq];
    const int tid = threadIdx.x;
    const int warp = tid >> 5, lane = tid & 31;

    for (int h = tid; h < Hq; h += 256) {
        sq[h] = q[b * Hq + h];
        sv[h] = vvec[h];
    }
    __syncthreads();

#pragma unroll
    for (int p = 0; p < 4; p++) {
        const int s = chunk * 32 + warp * 4 + p;
        const float* e = ep + (size_t)(b * Sq + s) * Hq;
        float sum = 0.0f;
        for (int h = lane; h < Hq; h += 32)
            sum += sv[h] * tanh_fast(sq[h] + e[h]);
#pragma unroll
        for (int o = 16; o > 0; o >>= 1)
            sum += __shfl_xor_sync(0xffffffffu, sum, o);
        if (lane == 0) scores[b * Sq + s] = sum;
    }
}

// ===========================================================================
// Softmax + context + x assembly: grid (B, 8); block handles 256 enc dims.
// Each block redundantly computes the (identical, deterministic) softmax.
// chunk 0 additionally writes the embedding part of x.
// ===========================================================================
__global__ __launch_bounds__(256)
void attn_ctx_kernel(const float* __restrict__ scores,
                     const float* __restrict__ enc,
                     const float* __restrict__ emb,
                     const int* __restrict__ tok,
                     __nv_bfloat16* __restrict__ xhi,
                     __nv_bfloat16* __restrict__ xlo,
                     int t) {
    const int b = blockIdx.x;
    const int chunk = blockIdx.y;   // 0..7
    __shared__ float sa[Sq];
    __shared__ float sred[8];
    const int tid = threadIdx.x;
    const int warp = tid >> 5, lane = tid & 31;

    float vs = (tid < Sq) ? scores[b * Sq + tid] : -3.0e38f;
    float m = vs;
#pragma unroll
    for (int o = 16; o > 0; o >>= 1)
        m = fmaxf(m, __shfl_xor_sync(0xffffffffu, m, o));
    if (lane == 0) sred[warp] = m;
    __syncthreads();
    if (tid == 0) {
        float mm = sred[0];
        for (int i = 1; i < 8; i++) mm = fmaxf(mm, sred[i]);
        sred[0] = mm;
    }
    __syncthreads();
    const float mx = sred[0];
    float e1 = (tid < Sq) ? __expf(vs - mx) : 0.0f;
    float ssum = e1;
#pragma unroll
    for (int o = 16; o > 0; o >>= 1)
        ssum += __shfl_xor_sync(0xffffffffu, ssum, o);
    __syncthreads();
    if (lane == 0) sred[warp] = ssum;
    __syncthreads();
    if (tid == 0) {
        float tt = 0.0f;
        for (int i = 0; i < 8; i++) tt += sred[i];
        sred[0] = tt;
    }
    __syncthreads();
    const float inv = __fdividef(1.0f, sred[0]);
    if (tid < Sq) sa[tid] = e1 * inv;
    __syncthreads();

    // context over this chunk's 256 dims
    const int d = chunk * 256 + tid;
    const float* eb = enc + (size_t)b * Sq * ENCq + d;
    float sum = 0.0f;
#pragma unroll 4
    for (int s = 0; s < Sq; s++)
        sum += sa[s] * eb[(size_t)s * ENCq];
    __nv_bfloat16 h, l;
    split_bf16(sum, &h, &l);
    xhi[b * KXq + Eq + d] = h;
    xlo[b * KXq + Eq + d] = l;

    if (chunk == 0) {
        const int tk = tok[b * Tq + t];
#pragma unroll
        for (int i = 0; i < 2; i++) {
            int e0 = tid + i * 256;
            float v = emb[(size_t)tk * Eq + e0];
            __nv_bfloat16 hh, ll;
            split_bf16(v, &hh, &ll);
            xhi[b * KXq + e0] = hh;
            xlo[b * KXq + e0] = ll;
        }
    }
}

// ===========================================================================
// GRU elementwise update (+ hi/lo split of h_new)
// ===========================================================================
__global__ void gru_kernel(const float* __restrict__ gi,
                           const float* __restrict__ gh,
                           const float* __restrict__ hprev,
                           float* __restrict__ hnew,
                           __nv_bfloat16* __restrict__ hhi,
                           __nv_bfloat16* __restrict__ hlo) {
    int i = blockIdx.x * blockDim.x + threadIdx.x;  // B*H = 65536
    int b = i >> 10, j = i & 1023;
    const float* a = gi + b * G3q;
    const float* c = gh + b * G3q;
    float r = sigmoid_fast(a[j] + c[j]);
    float z = sigmoid_fast(a[Hq + j] + c[Hq + j]);
    float n = tanh_fast(a[2 * Hq + j] + r * c[2 * Hq + j]);
    float hv = (1.0f - z) * n + z * hprev[i];
    hnew[i] = hv;
    __nv_bfloat16 h, l;
    split_bf16(hv, &h, &l);
    hhi[i] = h;
    hlo[i] = l;
}

// ===========================================================================
// Launch
// ===========================================================================
extern "C" void kernel_launch(void* const* d_in, const int* in_sizes, int n_in,
                              void* d_out, int out_size) {
    const float* enc  = (const float*)d_in[0];
    const float* h0in = (const float*)d_in[1];
    const int*   tgt  = (const int*)d_in[2];
    const float* emb  = (const float*)d_in[3];
    const float* Wa   = (const float*)d_in[4];
    const float* ba   = (const float*)d_in[5];
    const float* vvec = (const float*)d_in[6];
    const float* W_ih = (const float*)d_in[7];
    const float* b_ih = (const float*)d_in[8];
    const float* W_hh = (const float*)d_in[9];
    const float* b_hh = (const float*)d_in[10];
    const float* Wo   = (const float*)d_in[11];
    const float* bo   = (const float*)d_in[12];
    float* out = (float*)d_out;                  // [B, T, V]

    static bool init_done = false;
    static float *ep, *h0b, *h1b, *qp, *gip, *ghp, *scoresp;
    static __nv_bfloat16 *hhi0, *hhi1, *hlo0, *hlo1, *xhi, *xlo;
    static __nv_bfloat16 *Wohi, *Wolo, *Wihhi, *Wihlo, *Whhhi, *Whhlo;
    static __nv_bfloat16 *Waqhi, *Waqlo, *Waehi, *Waelo, *enchi, *enclo;
    static int* tokp;
    if (!init_done) {
        void* p;
        cudaGetSymbolAddress((void**)&ep, g_ep);
        cudaGetSymbolAddress(&p, g_h);    h0b = (float*)p; h1b = h0b + Bq * Hq;
        cudaGetSymbolAddress(&p, g_hhi);  hhi0 = (__nv_bfloat16*)p; hhi1 = hhi0 + Bq * Hq;
        cudaGetSymbolAddress(&p, g_hlo);  hlo0 = (__nv_bfloat16*)p; hlo1 = hlo0 + Bq * Hq;
        cudaGetSymbolAddress((void**)&qp, g_q);
        cudaGetSymbolAddress((void**)&scoresp, g_scores);
        cudaGetSymbolAddress((void**)&xhi, g_xhi);
        cudaGetSymbolAddress((void**)&xlo, g_xlo);
        cudaGetSymbolAddress((void**)&gip, g_gi);
        cudaGetSymbolAddress((void**)&ghp, g_gh);
        cudaGetSymbolAddress((void**)&Wohi, g_Wohi);
        cudaGetSymbolAddress((void**)&Wolo, g_Wolo);
        cudaGetSymbolAddress((void**)&Wihhi, g_Wihhi);
        cudaGetSymbolAddress((void**)&Wihlo, g_Wihlo);
        cudaGetSymbolAddress((void**)&Whhhi, g_Whhhi);
        cudaGetSymbolAddress((void**)&Whhlo, g_Whhlo);
        cudaGetSymbolAddress((void**)&Waqhi, g_Waqhi);
        cudaGetSymbolAddress((void**)&Waqlo, g_Waqlo);
        cudaGetSymbolAddress((void**)&Waehi, g_Waehi);
        cudaGetSymbolAddress((void**)&Waelo, g_Waelo);
        cudaGetSymbolAddress((void**)&enchi, g_enchi);
        cudaGetSymbolAddress((void**)&enclo, g_enclo);
        cudaGetSymbolAddress((void**)&tokp, g_tok);
        cudaFuncSetAttribute(gemm_mma2,
                             cudaFuncAttributeMaxDynamicSharedMemorySize,
                             GEMM_SMEM_BYTES);
        init_done = true;
    }

    prep_tokens_kernel<<<1, 256>>>(tgt, tokp);
    copy_kernel<<<(Bq * Hq + 255) / 256, 256>>>(h0in, h0b, Bq * Hq);
    split_kernel<<<(Bq * Hq + 255) / 256, 256>>>(h0in, Hq, Hq, 0, hhi0, hlo0, Bq * Hq);

    // Weight / encoder splits (constant across the run; recomputed each call)
    split_kernel<<<(Vq * Hq + 255) / 256, 256>>>(Wo, Hq, Hq, 0, Wohi, Wolo, Vq * Hq);
    split_kernel<<<(G3q * KXq + 255) / 256, 256>>>(W_ih, KXq, KXq, 0, Wihhi, Wihlo, G3q * KXq);
    split_kernel<<<(G3q * Hq + 255) / 256, 256>>>(W_hh, Hq, Hq, 0, Whhhi, Whhlo, G3q * Hq);
    split_kernel<<<(Hq * Hq + 255) / 256, 256>>>(Wa, Hq + ENCq, Hq, 0, Waqhi, Waqlo, Hq * Hq);
    split_kernel<<<(Hq * ENCq + 255) / 256, 256>>>(Wa, Hq + ENCq, ENCq, Hq, Waehi, Waelo, Hq * ENCq);
    split_kernel<<<(Bq * Sq * ENCq + 255) / 256, 256>>>(enc, ENCq, ENCq, 0, enchi, enclo, Bq * Sq * ENCq);

    // enc_proj: ep[pos*H + h] = enc[pos]·Wa_e[h]   (N=1024, Mact=8192, K=2048)
    gemm_mma2<<<dim3(Hq / 128, (Bq * Sq) / 64), 256, GEMM_SMEM_BYTES>>>(
        Waehi, Waelo, Hq, nullptr, nullptr, nullptr, nullptr,
        ep, Hq, nullptr, 0, enchi, enclo, ENCq);

    for (int t = 0; t < Tq; t++) {
        __nv_bfloat16* chi = (t & 1) ? hhi1 : hhi0;
        __nv_bfloat16* clo = (t & 1) ? hlo1 : hlo0;
        __nv_bfloat16* nhi = (t & 1) ? hhi0 : hhi1;
        __nv_bfloat16* nlo = (t & 1) ? hlo0 : hlo1;
        float* hc = (t & 1) ? h1b : h0b;
        float* hn = (t & 1) ? h0b : h1b;

        // fused q (rows 0..1023 -> qp) + gh (rows 1024..4095 -> ghp), K=1024
        gemm_mma2<<<dim3((Hq + G3q) / 128, 1), 256, GEMM_SMEM_BYTES>>>(
            Waqhi, Waqlo, Hq, Whhhi, Whhlo, ba, b_hh,
            qp, Hq, ghp, G3q, chi, clo, Hq);

        // attention scores + softmax/context/x
        attn_scores_kernel<<<dim3(Bq, 4), 256>>>(ep, qp, vvec, scoresp);
        attn_ctx_kernel<<<dim3(Bq, 8), 256>>>(scoresp, enc, emb, tokp, xhi, xlo, t);

        // gi = x @ W_ih^T + b_ih  (N=3072, K=2560)
        gemm_mma2<<<dim3(G3q / 128, 1), 256, GEMM_SMEM_BYTES>>>(
            Wihhi, Wihlo, G3q, nullptr, nullptr, b_ih, nullptr,
            gip, G3q, nullptr, 0, xhi, xlo, KXq);

        // GRU update (+ split of h_new)
        gru_kernel<<<(Bq * Hq) / 256, 256>>>(gip, ghp, hc, hn, nhi, nlo);

        // logits: out[:, t, :] = h_new @ Wo^T + bo  (N=16000, K=1024)
        gemm_mma2<<<dim3(Vq / 128, 1), 256, GEMM_SMEM_BYTES>>>(
            Wohi, Wolo, Vq, nullptr, nullptr, bo, nullptr,
            out + (size_t)t * Vq, (long long)Tq * Vq, nullptr, 0, nhi, nlo, Hq);
    }
}